// round 15
// baseline (speedup 1.0000x reference)
#include <cuda_runtime.h>
#include <cuda_fp16.h>
#include <cstdint>

// Problem constants (fixed by setup_inputs)
#define B_  2
#define S_  2048
#define D_  1024
#define H_  16
#define HD_ 64
#define M_  (B_ * S_)     // 4096
#define LOG2E 1.4426950408889634f

// ---------------------------------------------------------------------------
// Scratch (__device__ globals; no allocation allowed)
// ---------------------------------------------------------------------------
__device__ __half g_xh[(size_t)M_ * D_];            // x fp16
__device__ __half g_wc16[(size_t)4 * D_ * D_];      // Wq|Wk|Wv|Wo fp16 [4096,1024]
__device__ __half g_ac16[(size_t)M_ * D_];          // attn out fp16
__device__ __half g_qh[(size_t)M_ * D_];            // fp16 q (roped, scaled /8*log2e)
__device__ __half g_kh[(size_t)M_ * D_];            // fp16 k (roped)
__device__ __half g_vh[(size_t)M_ * D_];            // fp16 v

// ---------------------------------------------------------------------------
// Helpers
// ---------------------------------------------------------------------------
__device__ __forceinline__ uint32_t smem_u32(const void* p) {
    uint32_t a;
    asm("{ .reg .u64 t; cvta.to.shared.u64 t, %1; cvt.u32.u64 %0, t; }"
        : "=r"(a) : "l"(p));
    return a;
}
__device__ __forceinline__ uint32_t sw128(uint32_t o) { return o ^ ((o >> 3) & 0x70); }

__device__ __forceinline__ uint32_t pack_h2(float a, float b) {
    __half2 h = __floats2half2_rn(a, b);
    return *reinterpret_cast<uint32_t*>(&h);
}

#define CP_ASYNC16(saddr, gptr) \
    asm volatile("cp.async.cg.shared.global [%0], [%1], 16;" \
                 :: "r"(saddr), "l"(gptr) : "memory")
#define CP_COMMIT() asm volatile("cp.async.commit_group;" ::: "memory")
#define CP_WAIT1()  asm volatile("cp.async.wait_group 1;" ::: "memory")
#define CP_WAIT0()  asm volatile("cp.async.wait_group 0;" ::: "memory")

#define BAR_GROUP(id) \
    asm volatile("bar.sync %0, 128;" :: "r"(id) : "memory")

#define LDMATRIX_X4(r0, r1, r2, r3, addr) \
    asm volatile("ldmatrix.sync.aligned.m8n8.x4.shared.b16 {%0,%1,%2,%3}, [%4];" \
                 : "=r"(r0), "=r"(r1), "=r"(r2), "=r"(r3) : "r"(addr))
#define LDMATRIX_X4_T(r0, r1, r2, r3, addr) \
    asm volatile("ldmatrix.sync.aligned.m8n8.x4.trans.shared.b16 {%0,%1,%2,%3}, [%4];" \
                 : "=r"(r0), "=r"(r1), "=r"(r2), "=r"(r3) : "r"(addr))

#define MMA_F16(d, a, b) \
    asm volatile("mma.sync.aligned.m16n8k16.row.col.f32.f16.f16.f32 " \
                 "{%0,%1,%2,%3}, {%4,%5,%6,%7}, {%8,%9}, {%0,%1,%2,%3};" \
                 : "+f"((d)[0]), "+f"((d)[1]), "+f"((d)[2]), "+f"((d)[3]) \
                 : "r"((a)[0]), "r"((a)[1]), "r"((a)[2]), "r"((a)[3]),   \
                   "r"((b)[0]), "r"((b)[1]))

// ---------------------------------------------------------------------------
// Combined convert: x (2^21 float2) then Wq|Wk|Wv|Wo (4 x 2^19 float2) -> fp16
// ---------------------------------------------------------------------------
__global__ void conv_all_kernel(const float2* __restrict__ x,
                                const float2* __restrict__ w0,
                                const float2* __restrict__ w1,
                                const float2* __restrict__ w2,
                                const float2* __restrict__ w3,
                                __half2* __restrict__ xh,
                                __half2* __restrict__ wh)
{
    int p = blockIdx.x * blockDim.x + threadIdx.x;   // 0 .. 2^22-1
    if (p < (1 << 21)) {
        float2 v = x[p];
        xh[p] = __floats2half2_rn(v.x, v.y);
    } else {
        int q = p - (1 << 21);
        int w = q >> 19;
        int r = q & 524287;
        const float2* src = (w == 0) ? w0 : (w == 1) ? w1 : (w == 2) ? w2 : w3;
        float2 v = src[r];
        wh[q] = __floats2half2_rn(v.x, v.y);
    }
}

// ---------------------------------------------------------------------------
// HMMA fp16 GEMM (256 thr, 64x64 warp tiles, 3-stage). Unchanged (tensor 48%).
// A [M,1024] fp16, B fp16 [rows,1024]. K=1024 (16 chunks).
// mode 0: QKV fused (RoPE q/k log2-domain, plain v);  mode 1: fp32 out.
// ---------------------------------------------------------------------------
#define A_ST       16384
#define B_ST       32768
#define STAGE2     (A_ST + B_ST)
#define GEMM_SMEM  (3 * STAGE2)          // 144 KB
#define NCHUNK     16

__global__ __launch_bounds__(256, 1) void gemm_f16_kernel(
    const __half* __restrict__ A,
    const __half* __restrict__ Bw,
    float* __restrict__ C,
    __half* __restrict__ qh, __half* __restrict__ kh, __half* __restrict__ vh,
    const float* __restrict__ fc, const float* __restrict__ fs,
    int mode)
{
    extern __shared__ char dyn[];
    const int tid  = threadIdx.x;
    const int wid  = tid >> 5;
    const int lane = tid & 31;
    const int wm   = wid >> 2;
    const int wn   = wid & 3;
    const int m0   = blockIdx.y * 128;
    const int n0   = blockIdx.x * 256;
    const uint32_t smem = smem_u32(dyn);

    const int lrow = tid >> 3;
    const int lc16 = tid & 7;
    const __half* gA = A  + (size_t)(m0 + lrow) * 1024 + lc16 * 8;
    const __half* gB = Bw + (size_t)(n0 + lrow) * 1024 + lc16 * 8;
    const uint32_t sA0 = smem + sw128(lrow * 128 + lc16 * 16);
    const uint32_t sB0 = sA0 + A_ST;

#define PREFETCH(c, stg) do {                                                   \
    const __half* pa = gA + (size_t)(c) * 64;                                   \
    const __half* pb = gB + (size_t)(c) * 64;                                   \
    uint32_t off = (stg) * STAGE2;                                              \
    _Pragma("unroll")                                                           \
    for (int j = 0; j < 4; j++)                                                 \
        CP_ASYNC16(sA0 + off + j * 4096, pa + (size_t)j * 32 * 1024);           \
    _Pragma("unroll")                                                           \
    for (int j = 0; j < 8; j++)                                                 \
        CP_ASYNC16(sB0 + off + j * 4096, pb + (size_t)j * 32 * 1024);           \
    CP_COMMIT(); } while (0)

    float acc[4][8][4];
#pragma unroll
    for (int i = 0; i < 4; i++)
#pragma unroll
        for (int j = 0; j < 8; j++)
#pragma unroll
            for (int q = 0; q < 4; q++) acc[i][j][q] = 0.f;

    const int arow = wm * 64 + (lane & 15);
    const int acb0 = (lane >> 4) * 16;
    const int brow0 = wn * 64 + (lane & 7) + ((lane >> 4) << 3);
    const int bcb0 = ((lane >> 3) & 1) * 16;

    PREFETCH(0, 0);
    PREFETCH(1, 1);

    int s = 0, sp = 2;
    for (int c = 0; c < NCHUNK; c++) {
        if (c + 1 < NCHUNK) CP_WAIT1(); else CP_WAIT0();
        __syncthreads();
        if (c + 2 < NCHUNK) PREFETCH(c + 2, sp);

        const uint32_t abase = smem + s * STAGE2;
        const uint32_t bbase = abase + A_ST;

#pragma unroll
        for (int ks = 0; ks < 4; ks++) {
            uint32_t a[4][4];
#pragma unroll
            for (int mf = 0; mf < 4; mf++) {
                int row = arow + mf * 16;
                uint32_t addr = abase + row * 128 +
                    ((ks * 32 + acb0) ^ ((row & 7) << 4));
                LDMATRIX_X4(a[mf][0], a[mf][1], a[mf][2], a[mf][3], addr);
            }
#pragma unroll
            for (int nf2 = 0; nf2 < 4; nf2++) {
                int row = brow0 + nf2 * 16;
                uint32_t addr = bbase + row * 128 +
                    ((ks * 32 + bcb0) ^ ((row & 7) << 4));
                uint32_t r0, r1, r2, r3;
                LDMATRIX_X4(r0, r1, r2, r3, addr);
                uint32_t b0[2] = {r0, r1}, b1[2] = {r2, r3};
#pragma unroll
                for (int mf = 0; mf < 4; mf++) {
                    MMA_F16(acc[mf][nf2 * 2],     a[mf], b0);
                    MMA_F16(acc[mf][nf2 * 2 + 1], a[mf], b1);
                }
            }
        }
        s  = (s  == 2) ? 0 : s + 1;
        sp = (sp == 2) ? 0 : sp + 1;
    }
#undef PREFETCH

    if (mode == 1) {
#pragma unroll
        for (int mf = 0; mf < 4; mf++) {
            int r = m0 + wm * 64 + mf * 16 + (lane >> 2);
#pragma unroll
            for (int nf = 0; nf < 8; nf++) {
                int cN = n0 + wn * 64 + nf * 8 + (lane & 3) * 2;
                *(float2*)(C + (size_t)r * D_ + cN) =
                    make_float2(acc[mf][nf][0], acc[mf][nf][1]);
                *(float2*)(C + (size_t)(r + 8) * D_ + cN) =
                    make_float2(acc[mf][nf][2], acc[mf][nf][3]);
            }
        }
        return;
    }

    // mode 0: fused QKV epilogue (q scaled into log2 domain for exp2 softmax)
    const int w     = n0 >> 10;            // 0=q, 1=k, 2=v
    const int cbase = n0 & 1023;
#pragma unroll
    for (int mf = 0; mf < 4; mf++) {
        const int r0r = m0 + wm * 64 + mf * 16 + (lane >> 2);
#pragma unroll
        for (int nf = 0; nf < 8; nf++) {
            const int cN = cbase + wn * 64 + nf * 8 + (lane & 3) * 2;
            const int j  = (cN & 63) >> 1;
            if (w == 2) {
#pragma unroll
                for (int rr = 0; rr < 2; rr++) {
                    const int r = r0r + rr * 8;
                    *(__half2*)(vh + (size_t)r * D_ + cN) =
                        __floats2half2_rn(acc[mf][nf][rr * 2],
                                          acc[mf][nf][rr * 2 + 1]);
                }
            } else {
                __half* dst = (w == 0) ? qh : kh;
                const float qs = (w == 0) ? (0.125f * LOG2E) : 1.0f;
#pragma unroll
                for (int rr = 0; rr < 2; rr++) {
                    const int r = r0r + rr * 8;
                    const int srow = r & (S_ - 1);
                    const float cv = fc[srow * 32 + j];
                    const float sv = fs[srow * 32 + j];
                    float x0 = acc[mf][nf][rr * 2], x1 = acc[mf][nf][rr * 2 + 1];
                    *(__half2*)(dst + (size_t)r * D_ + cN) =
                        __floats2half2_rn((x0 * cv - x1 * sv) * qs,
                                          (x1 * cv + x0 * sv) * qs);
                }
            }
        }
    }
}

// ---------------------------------------------------------------------------
// HMMA fp16 causal flash attention — two independent 4-warp groups per CTA
// (R14 win) x LDSM-lean 32-row warp tiles (each K/V fragment feeds 4 MMAs).
// Group: 128-row q-tile, 4 warps x 32 rows, k-tile 64, own 3-stage pipeline,
// own named barrier. Smem = 2 x (Q 16K + 3 x 16K) = 128 KB. exp2 softmax.
// ---------------------------------------------------------------------------
#define ATT_GQ    16384
#define ATT_STAGE 16384
#define ATT_GRPB  (ATT_GQ + 3 * ATT_STAGE)          // 64 KB per group
#define ATT_SMEM  (2 * ATT_GRPB)                    // 128 KB

__global__ __launch_bounds__(256) void attn_hmma_kernel(
    const __half* __restrict__ qh, const __half* __restrict__ kh,
    const __half* __restrict__ vh, __half* __restrict__ oc)
{
    extern __shared__ char dyn[];
    const int tid  = threadIdx.x;
    const int wid  = tid >> 5;
    const int lane = tid & 31;
    const int grp  = wid >> 2;                 // 0 or 1
    const int wg   = wid & 3;                  // warp within group
    const int gt   = tid & 127;                // thread within group
    const int jq   = 2 * (7 - blockIdx.x) + grp;   // 128-row q-tile, heavy first
    const int bh = blockIdx.y;
    const int b  = bh >> 4;
    const int h  = bh & 15;
    const size_t base = (size_t)b * S_ * D_ + (size_t)h * HD_;
    const uint32_t smem = smem_u32(dyn);
    const uint32_t qbase = smem + grp * ATT_GRPB;
    const uint32_t sbase = qbase + ATT_GQ;
    const int barid = grp + 1;

    const int lrow = gt >> 3;                  // 0..15
    const int lc16 = gt & 7;
    const __half* gq = qh + base + (size_t)(jq * 128 + lrow) * D_ + lc16 * 8;
    const __half* gk = kh + base + (size_t)lrow * D_ + lc16 * 8;
    const __half* gv = vh + base + (size_t)lrow * D_ + lc16 * 8;

    const int ktmax = 2 * jq + 1;              // 64-row k tiles

    // Q tile: 128 rows x 128B (8 passes of 16 rows)
#pragma unroll
    for (int t = 0; t < 8; t++) {
        int row = lrow + t * 16;
        CP_ASYNC16(qbase + sw128(row * 128 + lc16 * 16),
                   gq + (size_t)t * 16 * D_);
    }

#define ATT_PREFETCH_NC(kt, stg) do {                                           \
    uint32_t sb = sbase + (stg) * ATT_STAGE;                                    \
    const __half* pk = gk + (size_t)(kt) * 64 * D_;                             \
    const __half* pv = gv + (size_t)(kt) * 64 * D_;                             \
    _Pragma("unroll")                                                           \
    for (int t = 0; t < 4; t++) {                                               \
        int row = lrow + t * 16;                                                \
        uint32_t so = sw128(row * 128 + lc16 * 16);                             \
        CP_ASYNC16(sb +        so, pk + (size_t)t * 16 * D_);                   \
        CP_ASYNC16(sb + 8192 + so, pv + (size_t)t * 16 * D_);                   \
    } } while (0)

    ATT_PREFETCH_NC(0, 0);
    CP_COMMIT();
    ATT_PREFETCH_NC(1, 1);    // ktmax >= 1 always
    CP_COMMIT();

    const int wq = wg * 32;                    // warp q-row base in group tile
    const int rbase = jq * 128 + wq + (lane >> 2);

    float m[2][2], l[2][2], oacc[2][8][4];
#pragma unroll
    for (int mf = 0; mf < 2; mf++) {
        m[mf][0] = m[mf][1] = -1e30f;
        l[mf][0] = l[mf][1] = 0.f;
#pragma unroll
        for (int j = 0; j < 8; j++)
#pragma unroll
            for (int q = 0; q < 4; q++) oacc[mf][j][q] = 0.f;
    }

    // hoist Q fragments after first wait (Q arrived with group 0's commit)
    uint32_t aq[2][4][4];
    bool aq_loaded = false;

    int s = 0, sp = 2;
    for (int kt = 0; kt <= ktmax; kt++) {
        if (kt + 1 <= ktmax) CP_WAIT1(); else CP_WAIT0();
        BAR_GROUP(barid);
        if (kt + 2 <= ktmax) { ATT_PREFETCH_NC(kt + 2, sp); CP_COMMIT(); }

        if (!aq_loaded) {
            aq_loaded = true;
#pragma unroll
            for (int mf = 0; mf < 2; mf++)
#pragma unroll
                for (int ks = 0; ks < 4; ks++) {
                    int row = wq + mf * 16 + (lane & 15);
                    uint32_t addr = qbase + row * 128 +
                        ((ks * 32 + (lane >> 4) * 16) ^ ((row & 7) << 4));
                    LDMATRIX_X4(aq[mf][ks][0], aq[mf][ks][1],
                                aq[mf][ks][2], aq[mf][ks][3], addr);
                }
        }

        const uint32_t kb = sbase + s * ATT_STAGE;
        const uint32_t vb = kb + 8192;

        // ---- S = Q K^T : warp tile 32(M) x 64(N), K=64 ----
        float sacc[2][8][4];
#pragma unroll
        for (int mf = 0; mf < 2; mf++)
#pragma unroll
            for (int nf = 0; nf < 8; nf++)
#pragma unroll
                for (int q4 = 0; q4 < 4; q4++) sacc[mf][nf][q4] = 0.f;

#pragma unroll
        for (int ks = 0; ks < 4; ks++) {
#pragma unroll
            for (int nf2 = 0; nf2 < 4; nf2++) {
                int row = nf2 * 16 + (lane & 7) + ((lane >> 4) << 3);
                uint32_t addr = kb + row * 128 +
                    ((ks * 32 + ((lane >> 3) & 1) * 16) ^ ((row & 7) << 4));
                uint32_t r0, r1, r2, r3;
                LDMATRIX_X4(r0, r1, r2, r3, addr);
                uint32_t b0[2] = {r0, r1}, b1[2] = {r2, r3};
#pragma unroll
                for (int mf = 0; mf < 2; mf++) {
                    MMA_F16(sacc[mf][nf2 * 2],     aq[mf][ks], b0);
                    MMA_F16(sacc[mf][nf2 * 2 + 1], aq[mf][ks], b1);
                }
            }
        }

        // ---- causal mask (diagonal band only) ----
        if (kt * 64 + 63 > jq * 128 + wq) {
#pragma unroll
            for (int mf = 0; mf < 2; mf++) {
                const int r = rbase + mf * 16;
#pragma unroll
                for (int nf = 0; nf < 8; nf++) {
                    int c0 = kt * 64 + nf * 8 + (lane & 3) * 2;
                    if (c0     > r)     sacc[mf][nf][0] = -1e30f;
                    if (c0 + 1 > r)     sacc[mf][nf][1] = -1e30f;
                    if (c0     > r + 8) sacc[mf][nf][2] = -1e30f;
                    if (c0 + 1 > r + 8) sacc[mf][nf][3] = -1e30f;
                }
            }
        }

        // ---- online softmax (per mf; 4-lane row groups) ----
        uint32_t phl[2][8], phh[2][8];
#pragma unroll
        for (int mf = 0; mf < 2; mf++) {
            float tml = -1e30f, tmh = -1e30f;
#pragma unroll
            for (int nf = 0; nf < 8; nf++) {
                tml = fmaxf(tml, fmaxf(sacc[mf][nf][0], sacc[mf][nf][1]));
                tmh = fmaxf(tmh, fmaxf(sacc[mf][nf][2], sacc[mf][nf][3]));
            }
            tml = fmaxf(tml, __shfl_xor_sync(0xffffffffu, tml, 1));
            tml = fmaxf(tml, __shfl_xor_sync(0xffffffffu, tml, 2));
            tmh = fmaxf(tmh, __shfl_xor_sync(0xffffffffu, tmh, 1));
            tmh = fmaxf(tmh, __shfl_xor_sync(0xffffffffu, tmh, 2));

            const float mln = fmaxf(m[mf][0], tml);
            const float mhn = fmaxf(m[mf][1], tmh);
            const float scl = exp2f(m[mf][0] - mln);
            const float sch = exp2f(m[mf][1] - mhn);
            m[mf][0] = mln; m[mf][1] = mhn;

            float sl = 0.f, sh = 0.f;
#pragma unroll
            for (int nf = 0; nf < 8; nf++) {
                float p0 = exp2f(sacc[mf][nf][0] - mln);
                float p1 = exp2f(sacc[mf][nf][1] - mln);
                float p2 = exp2f(sacc[mf][nf][2] - mhn);
                float p3 = exp2f(sacc[mf][nf][3] - mhn);
                sl += p0 + p1; sh += p2 + p3;
                phl[mf][nf] = pack_h2(p0, p1);
                phh[mf][nf] = pack_h2(p2, p3);
            }
            sl += __shfl_xor_sync(0xffffffffu, sl, 1);
            sl += __shfl_xor_sync(0xffffffffu, sl, 2);
            sh += __shfl_xor_sync(0xffffffffu, sh, 1);
            sh += __shfl_xor_sync(0xffffffffu, sh, 2);
            l[mf][0] = l[mf][0] * scl + sl;
            l[mf][1] = l[mf][1] * sch + sh;
#pragma unroll
            for (int nf = 0; nf < 8; nf++) {
                oacc[mf][nf][0] *= scl; oacc[mf][nf][1] *= scl;
                oacc[mf][nf][2] *= sch; oacc[mf][nf][3] *= sch;
            }
        }

        // ---- O += P V : each V fragment feeds both mf tiles ----
#pragma unroll
        for (int ksp = 0; ksp < 4; ksp++) {
            const int vrow = ksp * 16 + (lane & 7) + ((lane >> 3) & 1) * 8;
#pragma unroll
            for (int nd = 0; nd < 4; nd++) {
                uint32_t vaddr = vb + vrow * 128 +
                    ((nd * 32 + (lane >> 4) * 16) ^ ((vrow & 7) << 4));
                uint32_t r0, r1, r2, r3;
                LDMATRIX_X4_T(r0, r1, r2, r3, vaddr);
                uint32_t b0[2] = {r0, r1}, b1[2] = {r2, r3};
#pragma unroll
                for (int mf = 0; mf < 2; mf++) {
                    uint32_t pa[4] = { phl[mf][2 * ksp],     phh[mf][2 * ksp],
                                       phl[mf][2 * ksp + 1], phh[mf][2 * ksp + 1] };
                    MMA_F16(oacc[mf][nd * 2],     pa, b0);
                    MMA_F16(oacc[mf][nd * 2 + 1], pa, b1);
                }
            }
        }
        s  = (s  == 2) ? 0 : s + 1;
        sp = (sp == 2) ? 0 : sp + 1;
    }
#undef ATT_PREFETCH_NC

    // ---- epilogue: normalize, write fp16 attn into g_ac16 [M, 1024] ----
#pragma unroll
    for (int mf = 0; mf < 2; mf++) {
        const float il = 1.f / l[mf][0], ih = 1.f / l[mf][1];
        const int rowg = b * S_ + rbase + mf * 16;
#pragma unroll
        for (int nf = 0; nf < 8; nf++) {
            const int col = h * HD_ + nf * 8 + (lane & 3) * 2;
            *(__half2*)(oc + (size_t)rowg * D_ + col) =
                __floats2half2_rn(oacc[mf][nf][0] * il, oacc[mf][nf][1] * il);
            *(__half2*)(oc + (size_t)(rowg + 8) * D_ + col) =
                __floats2half2_rn(oacc[mf][nf][2] * ih, oacc[mf][nf][3] * ih);
        }
    }
}

// ---------------------------------------------------------------------------
// kernel_launch
// ---------------------------------------------------------------------------
extern "C" void kernel_launch(void* const* d_in, const int* in_sizes, int n_in,
                              void* d_out, int out_size)
{
    (void)in_sizes; (void)n_in; (void)out_size;
    const float* x  = (const float*)d_in[0];
    const float* fc = (const float*)d_in[1];
    const float* fs = (const float*)d_in[2];
    float* out = (float*)d_out;

    __half *xh, *wc, *ac, *qhp, *khp, *vhp;
    cudaGetSymbolAddress((void**)&xh, g_xh);
    cudaGetSymbolAddress((void**)&wc, g_wc16);
    cudaGetSymbolAddress((void**)&ac, g_ac16);
    cudaGetSymbolAddress((void**)&qhp, g_qh);
    cudaGetSymbolAddress((void**)&khp, g_kh);
    cudaGetSymbolAddress((void**)&vhp, g_vh);

    cudaFuncSetAttribute(gemm_f16_kernel,
                         cudaFuncAttributeMaxDynamicSharedMemorySize, GEMM_SMEM);
    cudaFuncSetAttribute(attn_hmma_kernel,
                         cudaFuncAttributeMaxDynamicSharedMemorySize, ATT_SMEM);

    // x + all 4 weights -> fp16 in one launch
    conv_all_kernel<<<(1 << 22) / 256, 256>>>(
        (const float2*)x,
        (const float2*)d_in[3], (const float2*)d_in[4],
        (const float2*)d_in[5], (const float2*)d_in[6],
        (__half2*)xh, (__half2*)wc);

    // Fused QKV projection + RoPE + v convert (grid 12 x 32)
    gemm_f16_kernel<<<dim3(12, M_ / 128), 256, GEMM_SMEM>>>(
        xh, wc, nullptr, qhp, khp, vhp, fc, fs, 0);

    // Flash attention (2 groups x 128-row q-tiles, 32-row warps) -> fp16 attn
    attn_hmma_kernel<<<dim3(8, 32), 256, ATT_SMEM>>>(qhp, khp, vhp, ac);

    // Output projection (K=1024; grid 4 x 32)
    gemm_f16_kernel<<<dim3(4, M_ / 128), 256, GEMM_SMEM>>>(
        ac, wc + (size_t)3 * D_ * D_, out, nullptr, nullptr, nullptr,
        nullptr, nullptr, 1);
}

// round 16
// speedup vs baseline: 1.0599x; 1.0599x over previous
#include <cuda_runtime.h>
#include <cuda_fp16.h>
#include <cstdint>

// Problem constants (fixed by setup_inputs)
#define B_  2
#define S_  2048
#define D_  1024
#define H_  16
#define HD_ 64
#define M_  (B_ * S_)     // 4096
#define LOG2E 1.4426950408889634f

// ---------------------------------------------------------------------------
// Scratch (__device__ globals; no allocation allowed)
// ---------------------------------------------------------------------------
__device__ __half g_xh[(size_t)M_ * D_];            // x fp16
__device__ __half g_wc16[(size_t)4 * D_ * D_];      // Wq|Wk|Wv|Wo fp16 [4096,1024]
__device__ __half g_ac16[(size_t)M_ * D_];          // attn out fp16
__device__ __half g_qh[(size_t)M_ * D_];            // fp16 q (roped, scaled /8*log2e)
__device__ __half g_kh[(size_t)M_ * D_];            // fp16 k (roped)
__device__ __half g_vh[(size_t)M_ * D_];            // fp16 v

// ---------------------------------------------------------------------------
// Helpers
// ---------------------------------------------------------------------------
__device__ __forceinline__ uint32_t smem_u32(const void* p) {
    uint32_t a;
    asm("{ .reg .u64 t; cvta.to.shared.u64 t, %1; cvt.u32.u64 %0, t; }"
        : "=r"(a) : "l"(p));
    return a;
}
__device__ __forceinline__ uint32_t sw128(uint32_t o) { return o ^ ((o >> 3) & 0x70); }

__device__ __forceinline__ uint32_t pack_h2(float a, float b) {
    __half2 h = __floats2half2_rn(a, b);
    return *reinterpret_cast<uint32_t*>(&h);
}
__device__ __forceinline__ float ex2(float x) {   // guaranteed single MUFU.EX2
    float r;
    asm("ex2.approx.f32 %0, %1;" : "=f"(r) : "f"(x));
    return r;
}

#define CP_ASYNC16(saddr, gptr) \
    asm volatile("cp.async.cg.shared.global [%0], [%1], 16;" \
                 :: "r"(saddr), "l"(gptr) : "memory")
#define CP_COMMIT() asm volatile("cp.async.commit_group;" ::: "memory")
#define CP_WAIT1()  asm volatile("cp.async.wait_group 1;" ::: "memory")
#define CP_WAIT0()  asm volatile("cp.async.wait_group 0;" ::: "memory")

#define BAR_GROUP(id) \
    asm volatile("bar.sync %0, 128;" :: "r"(id) : "memory")

#define LDMATRIX_X4(r0, r1, r2, r3, addr) \
    asm volatile("ldmatrix.sync.aligned.m8n8.x4.shared.b16 {%0,%1,%2,%3}, [%4];" \
                 : "=r"(r0), "=r"(r1), "=r"(r2), "=r"(r3) : "r"(addr))
#define LDMATRIX_X4_T(r0, r1, r2, r3, addr) \
    asm volatile("ldmatrix.sync.aligned.m8n8.x4.trans.shared.b16 {%0,%1,%2,%3}, [%4];" \
                 : "=r"(r0), "=r"(r1), "=r"(r2), "=r"(r3) : "r"(addr))

#define MMA_F16(d, a, b) \
    asm volatile("mma.sync.aligned.m16n8k16.row.col.f32.f16.f16.f32 " \
                 "{%0,%1,%2,%3}, {%4,%5,%6,%7}, {%8,%9}, {%0,%1,%2,%3};" \
                 : "+f"((d)[0]), "+f"((d)[1]), "+f"((d)[2]), "+f"((d)[3]) \
                 : "r"((a)[0]), "r"((a)[1]), "r"((a)[2]), "r"((a)[3]),   \
                   "r"((b)[0]), "r"((b)[1]))

// ---------------------------------------------------------------------------
// Combined convert: x (2^21 float2) then Wq|Wk|Wv|Wo (4 x 2^19 float2) -> fp16
// ---------------------------------------------------------------------------
__global__ void conv_all_kernel(const float2* __restrict__ x,
                                const float2* __restrict__ w0,
                                const float2* __restrict__ w1,
                                const float2* __restrict__ w2,
                                const float2* __restrict__ w3,
                                __half2* __restrict__ xh,
                                __half2* __restrict__ wh)
{
    int p = blockIdx.x * blockDim.x + threadIdx.x;   // 0 .. 2^22-1
    if (p < (1 << 21)) {
        float2 v = x[p];
        xh[p] = __floats2half2_rn(v.x, v.y);
    } else {
        int q = p - (1 << 21);
        int w = q >> 19;
        int r = q & 524287;
        const float2* src = (w == 0) ? w0 : (w == 1) ? w1 : (w == 2) ? w2 : w3;
        float2 v = src[r];
        wh[q] = __floats2half2_rn(v.x, v.y);
    }
}

// ---------------------------------------------------------------------------
// HMMA fp16 GEMM (256 thr, 64x64 warp tiles, 3-stage). Unchanged (tensor 48%).
// A [M,1024] fp16, B fp16 [rows,1024]. K=1024 (16 chunks).
// mode 0: QKV fused (RoPE q/k log2-domain, plain v);  mode 1: fp32 out.
// ---------------------------------------------------------------------------
#define A_ST       16384
#define B_ST       32768
#define STAGE2     (A_ST + B_ST)
#define GEMM_SMEM  (3 * STAGE2)          // 144 KB
#define NCHUNK     16

__global__ __launch_bounds__(256, 1) void gemm_f16_kernel(
    const __half* __restrict__ A,
    const __half* __restrict__ Bw,
    float* __restrict__ C,
    __half* __restrict__ qh, __half* __restrict__ kh, __half* __restrict__ vh,
    const float* __restrict__ fc, const float* __restrict__ fs,
    int mode)
{
    extern __shared__ char dyn[];
    const int tid  = threadIdx.x;
    const int wid  = tid >> 5;
    const int lane = tid & 31;
    const int wm   = wid >> 2;
    const int wn   = wid & 3;
    const int m0   = blockIdx.y * 128;
    const int n0   = blockIdx.x * 256;
    const uint32_t smem = smem_u32(dyn);

    const int lrow = tid >> 3;
    const int lc16 = tid & 7;
    const __half* gA = A  + (size_t)(m0 + lrow) * 1024 + lc16 * 8;
    const __half* gB = Bw + (size_t)(n0 + lrow) * 1024 + lc16 * 8;
    const uint32_t sA0 = smem + sw128(lrow * 128 + lc16 * 16);
    const uint32_t sB0 = sA0 + A_ST;

#define PREFETCH(c, stg) do {                                                   \
    const __half* pa = gA + (size_t)(c) * 64;                                   \
    const __half* pb = gB + (size_t)(c) * 64;                                   \
    uint32_t off = (stg) * STAGE2;                                              \
    _Pragma("unroll")                                                           \
    for (int j = 0; j < 4; j++)                                                 \
        CP_ASYNC16(sA0 + off + j * 4096, pa + (size_t)j * 32 * 1024);           \
    _Pragma("unroll")                                                           \
    for (int j = 0; j < 8; j++)                                                 \
        CP_ASYNC16(sB0 + off + j * 4096, pb + (size_t)j * 32 * 1024);           \
    CP_COMMIT(); } while (0)

    float acc[4][8][4];
#pragma unroll
    for (int i = 0; i < 4; i++)
#pragma unroll
        for (int j = 0; j < 8; j++)
#pragma unroll
            for (int q = 0; q < 4; q++) acc[i][j][q] = 0.f;

    const int arow = wm * 64 + (lane & 15);
    const int acb0 = (lane >> 4) * 16;
    const int brow0 = wn * 64 + (lane & 7) + ((lane >> 4) << 3);
    const int bcb0 = ((lane >> 3) & 1) * 16;

    PREFETCH(0, 0);
    PREFETCH(1, 1);

    int s = 0, sp = 2;
    for (int c = 0; c < NCHUNK; c++) {
        if (c + 1 < NCHUNK) CP_WAIT1(); else CP_WAIT0();
        __syncthreads();
        if (c + 2 < NCHUNK) PREFETCH(c + 2, sp);

        const uint32_t abase = smem + s * STAGE2;
        const uint32_t bbase = abase + A_ST;

#pragma unroll
        for (int ks = 0; ks < 4; ks++) {
            uint32_t a[4][4];
#pragma unroll
            for (int mf = 0; mf < 4; mf++) {
                int row = arow + mf * 16;
                uint32_t addr = abase + row * 128 +
                    ((ks * 32 + acb0) ^ ((row & 7) << 4));
                LDMATRIX_X4(a[mf][0], a[mf][1], a[mf][2], a[mf][3], addr);
            }
#pragma unroll
            for (int nf2 = 0; nf2 < 4; nf2++) {
                int row = brow0 + nf2 * 16;
                uint32_t addr = bbase + row * 128 +
                    ((ks * 32 + bcb0) ^ ((row & 7) << 4));
                uint32_t r0, r1, r2, r3;
                LDMATRIX_X4(r0, r1, r2, r3, addr);
                uint32_t b0[2] = {r0, r1}, b1[2] = {r2, r3};
#pragma unroll
                for (int mf = 0; mf < 4; mf++) {
                    MMA_F16(acc[mf][nf2 * 2],     a[mf], b0);
                    MMA_F16(acc[mf][nf2 * 2 + 1], a[mf], b1);
                }
            }
        }
        s  = (s  == 2) ? 0 : s + 1;
        sp = (sp == 2) ? 0 : sp + 1;
    }
#undef PREFETCH

    if (mode == 1) {
#pragma unroll
        for (int mf = 0; mf < 4; mf++) {
            int r = m0 + wm * 64 + mf * 16 + (lane >> 2);
#pragma unroll
            for (int nf = 0; nf < 8; nf++) {
                int cN = n0 + wn * 64 + nf * 8 + (lane & 3) * 2;
                *(float2*)(C + (size_t)r * D_ + cN) =
                    make_float2(acc[mf][nf][0], acc[mf][nf][1]);
                *(float2*)(C + (size_t)(r + 8) * D_ + cN) =
                    make_float2(acc[mf][nf][2], acc[mf][nf][3]);
            }
        }
        return;
    }

    // mode 0: fused QKV epilogue (q scaled into log2 domain for exp2 softmax)
    const int w     = n0 >> 10;            // 0=q, 1=k, 2=v
    const int cbase = n0 & 1023;
#pragma unroll
    for (int mf = 0; mf < 4; mf++) {
        const int r0r = m0 + wm * 64 + mf * 16 + (lane >> 2);
#pragma unroll
        for (int nf = 0; nf < 8; nf++) {
            const int cN = cbase + wn * 64 + nf * 8 + (lane & 3) * 2;
            const int j  = (cN & 63) >> 1;
            if (w == 2) {
#pragma unroll
                for (int rr = 0; rr < 2; rr++) {
                    const int r = r0r + rr * 8;
                    *(__half2*)(vh + (size_t)r * D_ + cN) =
                        __floats2half2_rn(acc[mf][nf][rr * 2],
                                          acc[mf][nf][rr * 2 + 1]);
                }
            } else {
                __half* dst = (w == 0) ? qh : kh;
                const float qs = (w == 0) ? (0.125f * LOG2E) : 1.0f;
#pragma unroll
                for (int rr = 0; rr < 2; rr++) {
                    const int r = r0r + rr * 8;
                    const int srow = r & (S_ - 1);
                    const float cv = fc[srow * 32 + j];
                    const float sv = fs[srow * 32 + j];
                    float x0 = acc[mf][nf][rr * 2], x1 = acc[mf][nf][rr * 2 + 1];
                    *(__half2*)(dst + (size_t)r * D_ + cN) =
                        __floats2half2_rn((x0 * cv - x1 * sv) * qs,
                                          (x1 * cv + x0 * sv) * qs);
                }
            }
        }
    }
}

// ---------------------------------------------------------------------------
// HMMA fp16 causal flash attention — round-14 config (measured best):
// TWO independent 4-warp groups per CTA, each with its own 64-row q-tile,
// Q smem, 3-stage K/V pipeline (k-tile 128), named barrier.
// Smem = 2 x Q 8K + 2 x 3 x (K 16K + V 16K) = 208 KB.
// exp2-domain softmax via single-instruction MUFU ex2.approx.
// ---------------------------------------------------------------------------
#define ATT_GQ    8192
#define ATT_STAGE 32768
#define ATT_SMEM  (2 * ATT_GQ + 2 * 3 * ATT_STAGE)   // 208 KB

__global__ __launch_bounds__(256) void attn_hmma_kernel(
    const __half* __restrict__ qh, const __half* __restrict__ kh,
    const __half* __restrict__ vh, __half* __restrict__ oc)
{
    extern __shared__ char dyn[];
    const int tid  = threadIdx.x;
    const int wid  = tid >> 5;
    const int lane = tid & 31;
    const int grp  = wid >> 2;                // 0 or 1
    const int wg   = wid & 3;                 // warp within group
    const int gt   = tid & 127;               // thread within group
    const int jq   = 2 * (15 - blockIdx.x) + grp;   // 64-row q-tile idx, heavy first
    const int bh = blockIdx.y;
    const int b  = bh >> 4;
    const int h  = bh & 15;
    const size_t base = (size_t)b * S_ * D_ + (size_t)h * HD_;
    const uint32_t smem = smem_u32(dyn);
    const uint32_t qbase = smem + grp * ATT_GQ;
    const uint32_t sbase = smem + 2 * ATT_GQ + grp * 3 * ATT_STAGE;
    const int barid = grp + 1;

    const int lrow = gt >> 3;                 // 0..15
    const int lc16 = gt & 7;
    const __half* gq = qh + base + (size_t)(jq * 64 + lrow) * D_ + lc16 * 8;
    const __half* gk = kh + base + (size_t)lrow * D_ + lc16 * 8;
    const __half* gv = vh + base + (size_t)lrow * D_ + lc16 * 8;

    const int ktmax = (jq * 64 + 63) >> 7;    // last 128-wide k tile

    // Q tile: 64 rows x 128B (4 passes of 16 rows)
#pragma unroll
    for (int t = 0; t < 4; t++) {
        int row = lrow + t * 16;
        CP_ASYNC16(qbase + sw128(row * 128 + lc16 * 16),
                   gq + (size_t)t * 16 * D_);
    }

#define ATT_PREFETCH_NC(kt, stg) do {                                           \
    uint32_t sb = sbase + (stg) * ATT_STAGE;                                    \
    const __half* pk = gk + (size_t)(kt) * 128 * D_;                            \
    const __half* pv = gv + (size_t)(kt) * 128 * D_;                            \
    _Pragma("unroll")                                                           \
    for (int t = 0; t < 8; t++) {                                               \
        int row = lrow + t * 16;                                                \
        uint32_t so = sw128(row * 128 + lc16 * 16);                             \
        CP_ASYNC16(sb +         so, pk + (size_t)t * 16 * D_);                  \
        CP_ASYNC16(sb + 16384 + so, pv + (size_t)t * 16 * D_);                  \
    } } while (0)

    ATT_PREFETCH_NC(0, 0);
    CP_COMMIT();
    if (ktmax >= 1) { ATT_PREFETCH_NC(1, 1); CP_COMMIT(); }

    float ml = -1e30f, mh = -1e30f, ll = 0.f, lh = 0.f;
    float oacc[8][4];
#pragma unroll
    for (int i = 0; i < 8; i++)
#pragma unroll
        for (int j = 0; j < 4; j++) oacc[i][j] = 0.f;

    const int rowl_g = jq * 64 + wg * 16 + (lane >> 2);

    int s = 0, sp = 2;
    for (int kt = 0; kt <= ktmax; kt++) {
        if (kt + 1 <= ktmax) CP_WAIT1(); else CP_WAIT0();
        BAR_GROUP(barid);
        if (kt + 2 <= ktmax) { ATT_PREFETCH_NC(kt + 2, sp); CP_COMMIT(); }

        const uint32_t kb = sbase + s * ATT_STAGE;
        const uint32_t vb = kb + 16384;

        float sacc[16][4];
#pragma unroll
        for (int nf = 0; nf < 16; nf++)
#pragma unroll
            for (int q4 = 0; q4 < 4; q4++) sacc[nf][q4] = 0.f;

#pragma unroll
        for (int ks = 0; ks < 4; ks++) {
            const int arow = wg * 16 + (lane & 15);
            uint32_t aaddr = qbase + arow * 128 +
                ((ks * 32 + (lane >> 4) * 16) ^ ((arow & 7) << 4));
            uint32_t a[4];
            LDMATRIX_X4(a[0], a[1], a[2], a[3], aaddr);
#pragma unroll
            for (int nf2 = 0; nf2 < 8; nf2++) {
                const int brow = nf2 * 16 + (lane & 7) + ((lane >> 4) << 3);
                uint32_t baddr = kb + brow * 128 +
                    ((ks * 32 + ((lane >> 3) & 1) * 16) ^ ((brow & 7) << 4));
                uint32_t r0, r1, r2, r3;
                LDMATRIX_X4(r0, r1, r2, r3, baddr);
                uint32_t b0[2] = {r0, r1}, b1[2] = {r2, r3};
                MMA_F16(sacc[nf2 * 2],     a, b0);
                MMA_F16(sacc[nf2 * 2 + 1], a, b1);
            }
        }

        if (kt == ktmax) {
#pragma unroll
            for (int nf = 0; nf < 16; nf++) {
                int c0 = kt * 128 + nf * 8 + (lane & 3) * 2;
                if (c0     > rowl_g)     sacc[nf][0] = -1e30f;
                if (c0 + 1 > rowl_g)     sacc[nf][1] = -1e30f;
                if (c0     > rowl_g + 8) sacc[nf][2] = -1e30f;
                if (c0 + 1 > rowl_g + 8) sacc[nf][3] = -1e30f;
            }
        }

        float tml = -1e30f, tmh = -1e30f;
#pragma unroll
        for (int nf = 0; nf < 16; nf++) {
            tml = fmaxf(tml, fmaxf(sacc[nf][0], sacc[nf][1]));
            tmh = fmaxf(tmh, fmaxf(sacc[nf][2], sacc[nf][3]));
        }
        tml = fmaxf(tml, __shfl_xor_sync(0xffffffffu, tml, 1));
        tml = fmaxf(tml, __shfl_xor_sync(0xffffffffu, tml, 2));
        tmh = fmaxf(tmh, __shfl_xor_sync(0xffffffffu, tmh, 1));
        tmh = fmaxf(tmh, __shfl_xor_sync(0xffffffffu, tmh, 2));

        const float mln = fmaxf(ml, tml), mhn = fmaxf(mh, tmh);
        const float scl = ex2(ml - mln), sch = ex2(mh - mhn);
        ml = mln; mh = mhn;

        uint32_t phl[16], phh[16];
        float sl = 0.f, sh = 0.f;
#pragma unroll
        for (int nf = 0; nf < 16; nf++) {
            float p0 = ex2(sacc[nf][0] - mln);
            float p1 = ex2(sacc[nf][1] - mln);
            float p2 = ex2(sacc[nf][2] - mhn);
            float p3 = ex2(sacc[nf][3] - mhn);
            sl += p0 + p1; sh += p2 + p3;
            phl[nf] = pack_h2(p0, p1);
            phh[nf] = pack_h2(p2, p3);
        }
        sl += __shfl_xor_sync(0xffffffffu, sl, 1);
        sl += __shfl_xor_sync(0xffffffffu, sl, 2);
        sh += __shfl_xor_sync(0xffffffffu, sh, 1);
        sh += __shfl_xor_sync(0xffffffffu, sh, 2);
        ll = ll * scl + sl;
        lh = lh * sch + sh;
#pragma unroll
        for (int onf = 0; onf < 8; onf++) {
            oacc[onf][0] *= scl; oacc[onf][1] *= scl;
            oacc[onf][2] *= sch; oacc[onf][3] *= sch;
        }

#pragma unroll
        for (int ksp = 0; ksp < 8; ksp++) {
            uint32_t a[4] = { phl[2 * ksp], phh[2 * ksp],
                              phl[2 * ksp + 1], phh[2 * ksp + 1] };
            const int vrow = ksp * 16 + (lane & 7) + ((lane >> 3) & 1) * 8;
#pragma unroll
            for (int nd = 0; nd < 4; nd++) {
                uint32_t vaddr = vb + vrow * 128 +
                    ((nd * 32 + (lane >> 4) * 16) ^ ((vrow & 7) << 4));
                uint32_t r0, r1, r2, r3;
                LDMATRIX_X4_T(r0, r1, r2, r3, vaddr);
                uint32_t b0[2] = {r0, r1}, b1[2] = {r2, r3};
                MMA_F16(oacc[nd * 2],     a, b0);
                MMA_F16(oacc[nd * 2 + 1], a, b1);
            }
        }
        s  = (s  == 2) ? 0 : s + 1;
        sp = (sp == 2) ? 0 : sp + 1;
    }
#undef ATT_PREFETCH_NC

    // ---- epilogue: normalize, write fp16 attn into g_ac16 [M, 1024] ----
    const float il = 1.f / ll, ih = 1.f / lh;
    const int rowg = b * S_ + rowl_g;
#pragma unroll
    for (int nf = 0; nf < 8; nf++) {
        const int col = h * HD_ + nf * 8 + (lane & 3) * 2;
        *(__half2*)(oc + (size_t)rowg * D_ + col) =
            __floats2half2_rn(oacc[nf][0] * il, oacc[nf][1] * il);
        *(__half2*)(oc + (size_t)(rowg + 8) * D_ + col) =
            __floats2half2_rn(oacc[nf][2] * ih, oacc[nf][3] * ih);
    }
}

// ---------------------------------------------------------------------------
// kernel_launch
// ---------------------------------------------------------------------------
extern "C" void kernel_launch(void* const* d_in, const int* in_sizes, int n_in,
                              void* d_out, int out_size)
{
    (void)in_sizes; (void)n_in; (void)out_size;
    const float* x  = (const float*)d_in[0];
    const float* fc = (const float*)d_in[1];
    const float* fs = (const float*)d_in[2];
    float* out = (float*)d_out;

    __half *xh, *wc, *ac, *qhp, *khp, *vhp;
    cudaGetSymbolAddress((void**)&xh, g_xh);
    cudaGetSymbolAddress((void**)&wc, g_wc16);
    cudaGetSymbolAddress((void**)&ac, g_ac16);
    cudaGetSymbolAddress((void**)&qhp, g_qh);
    cudaGetSymbolAddress((void**)&khp, g_kh);
    cudaGetSymbolAddress((void**)&vhp, g_vh);

    cudaFuncSetAttribute(gemm_f16_kernel,
                         cudaFuncAttributeMaxDynamicSharedMemorySize, GEMM_SMEM);
    cudaFuncSetAttribute(attn_hmma_kernel,
                         cudaFuncAttributeMaxDynamicSharedMemorySize, ATT_SMEM);

    // x + all 4 weights -> fp16 in one launch
    conv_all_kernel<<<(1 << 22) / 256, 256>>>(
        (const float2*)x,
        (const float2*)d_in[3], (const float2*)d_in[4],
        (const float2*)d_in[5], (const float2*)d_in[6],
        (__half2*)xh, (__half2*)wc);

    // Fused QKV projection + RoPE + v convert (grid 12 x 32)
    gemm_f16_kernel<<<dim3(12, M_ / 128), 256, GEMM_SMEM>>>(
        xh, wc, nullptr, qhp, khp, vhp, fc, fs, 0);

    // Flash attention (2 independent warp groups per CTA) -> fp16 attn
    attn_hmma_kernel<<<dim3(16, 32), 256, ATT_SMEM>>>(qhp, khp, vhp, ac);

    // Output projection (K=1024; grid 4 x 32)
    gemm_f16_kernel<<<dim3(4, M_ / 128), 256, GEMM_SMEM>>>(
        ac, wc + (size_t)3 * D_ * D_, out, nullptr, nullptr, nullptr,
        nullptr, nullptr, 1);
}

// round 17
// speedup vs baseline: 1.1120x; 1.0492x over previous
#include <cuda_runtime.h>
#include <cuda_fp16.h>
#include <cstdint>

// Problem constants (fixed by setup_inputs)
#define B_  2
#define S_  2048
#define D_  1024
#define H_  16
#define HD_ 64
#define M_  (B_ * S_)     // 4096
#define LOG2E 1.4426950408889634f

// ---------------------------------------------------------------------------
// Scratch (__device__ globals; no allocation allowed)
// ---------------------------------------------------------------------------
__device__ __half g_xh[(size_t)M_ * D_];            // x fp16
__device__ __half g_wc16[(size_t)4 * D_ * D_];      // Wq|Wk|Wv|Wo fp16 [4096,1024]
__device__ __half g_ac16[(size_t)M_ * D_];          // attn out fp16
__device__ __half g_qh[(size_t)M_ * D_];            // fp16 q (roped, scaled /8*log2e)
__device__ __half g_kh[(size_t)M_ * D_];            // fp16 k (roped)
__device__ __half g_vh[(size_t)M_ * D_];            // fp16 v
__device__ int    g_sync[32];                       // per-128-row readiness counters

// ---------------------------------------------------------------------------
// Helpers
// ---------------------------------------------------------------------------
__device__ __forceinline__ uint32_t smem_u32(const void* p) {
    uint32_t a;
    asm("{ .reg .u64 t; cvta.to.shared.u64 t, %1; cvt.u32.u64 %0, t; }"
        : "=r"(a) : "l"(p));
    return a;
}
__device__ __forceinline__ uint32_t sw128(uint32_t o) { return o ^ ((o >> 3) & 0x70); }

__device__ __forceinline__ uint32_t pack_h2(float a, float b) {
    __half2 h = __floats2half2_rn(a, b);
    return *reinterpret_cast<uint32_t*>(&h);
}
__device__ __forceinline__ float ex2(float x) {
    float r;
    asm("ex2.approx.f32 %0, %1;" : "=f"(r) : "f"(x));
    return r;
}

#define CP_ASYNC16(saddr, gptr) \
    asm volatile("cp.async.cg.shared.global [%0], [%1], 16;" \
                 :: "r"(saddr), "l"(gptr) : "memory")
#define CP_COMMIT() asm volatile("cp.async.commit_group;" ::: "memory")
#define CP_WAIT1()  asm volatile("cp.async.wait_group 1;" ::: "memory")
#define CP_WAIT0()  asm volatile("cp.async.wait_group 0;" ::: "memory")

#define BAR_GROUP(id) \
    asm volatile("bar.sync %0, 128;" :: "r"(id) : "memory")

#define LDMATRIX_X4(r0, r1, r2, r3, addr) \
    asm volatile("ldmatrix.sync.aligned.m8n8.x4.shared.b16 {%0,%1,%2,%3}, [%4];" \
                 : "=r"(r0), "=r"(r1), "=r"(r2), "=r"(r3) : "r"(addr))
#define LDMATRIX_X4_T(r0, r1, r2, r3, addr) \
    asm volatile("ldmatrix.sync.aligned.m8n8.x4.trans.shared.b16 {%0,%1,%2,%3}, [%4];" \
                 : "=r"(r0), "=r"(r1), "=r"(r2), "=r"(r3) : "r"(addr))

#define MMA_F16(d, a, b) \
    asm volatile("mma.sync.aligned.m16n8k16.row.col.f32.f16.f16.f32 " \
                 "{%0,%1,%2,%3}, {%4,%5,%6,%7}, {%8,%9}, {%0,%1,%2,%3};" \
                 : "+f"((d)[0]), "+f"((d)[1]), "+f"((d)[2]), "+f"((d)[3]) \
                 : "r"((a)[0]), "r"((a)[1]), "r"((a)[2]), "r"((a)[3]),   \
                   "r"((b)[0]), "r"((b)[1]))

// ---------------------------------------------------------------------------
// Combined convert: x + weights -> fp16; also zeroes the sync counters.
// ---------------------------------------------------------------------------
__global__ void conv_all_kernel(const float2* __restrict__ x,
                                const float2* __restrict__ w0,
                                const float2* __restrict__ w1,
                                const float2* __restrict__ w2,
                                const float2* __restrict__ w3,
                                __half2* __restrict__ xh,
                                __half2* __restrict__ wh)
{
    int p = blockIdx.x * blockDim.x + threadIdx.x;   // 0 .. 2^22-1
    if (p < 32) g_sync[p] = 0;
    if (p < (1 << 21)) {
        float2 v = x[p];
        xh[p] = __floats2half2_rn(v.x, v.y);
    } else {
        int q = p - (1 << 21);
        int w = q >> 19;
        int r = q & 524287;
        const float2* src = (w == 0) ? w0 : (w == 1) ? w1 : (w == 2) ? w2 : w3;
        float2 v = src[r];
        wh[q] = __floats2half2_rn(v.x, v.y);
    }
}

// ---------------------------------------------------------------------------
// HMMA fp16 GEMM (256 thr, 64x64 warp tiles, 3-stage) — QKV only (mode 0).
// ---------------------------------------------------------------------------
#define A_ST       16384
#define B_ST       32768
#define STAGE2     (A_ST + B_ST)
#define GEMM_SMEM  (3 * STAGE2)          // 144 KB
#define NCHUNK     16

__global__ __launch_bounds__(256, 1) void gemm_qkv_kernel(
    const __half* __restrict__ A,
    const __half* __restrict__ Bw,
    __half* __restrict__ qh, __half* __restrict__ kh, __half* __restrict__ vh,
    const float* __restrict__ fc, const float* __restrict__ fs)
{
    extern __shared__ char dyn[];
    const int tid  = threadIdx.x;
    const int wid  = tid >> 5;
    const int lane = tid & 31;
    const int wm   = wid >> 2;
    const int wn   = wid & 3;
    const int m0   = blockIdx.y * 128;
    const int n0   = blockIdx.x * 256;
    const uint32_t smem = smem_u32(dyn);

    const int lrow = tid >> 3;
    const int lc16 = tid & 7;
    const __half* gA = A  + (size_t)(m0 + lrow) * 1024 + lc16 * 8;
    const __half* gB = Bw + (size_t)(n0 + lrow) * 1024 + lc16 * 8;
    const uint32_t sA0 = smem + sw128(lrow * 128 + lc16 * 16);
    const uint32_t sB0 = sA0 + A_ST;

#define PREFETCH(c, stg) do {                                                   \
    const __half* pa = gA + (size_t)(c) * 64;                                   \
    const __half* pb = gB + (size_t)(c) * 64;                                   \
    uint32_t off = (stg) * STAGE2;                                              \
    _Pragma("unroll")                                                           \
    for (int j = 0; j < 4; j++)                                                 \
        CP_ASYNC16(sA0 + off + j * 4096, pa + (size_t)j * 32 * 1024);           \
    _Pragma("unroll")                                                           \
    for (int j = 0; j < 8; j++)                                                 \
        CP_ASYNC16(sB0 + off + j * 4096, pb + (size_t)j * 32 * 1024);           \
    CP_COMMIT(); } while (0)

    float acc[4][8][4];
#pragma unroll
    for (int i = 0; i < 4; i++)
#pragma unroll
        for (int j = 0; j < 8; j++)
#pragma unroll
            for (int q = 0; q < 4; q++) acc[i][j][q] = 0.f;

    const int arow = wm * 64 + (lane & 15);
    const int acb0 = (lane >> 4) * 16;
    const int brow0 = wn * 64 + (lane & 7) + ((lane >> 4) << 3);
    const int bcb0 = ((lane >> 3) & 1) * 16;

    PREFETCH(0, 0);
    PREFETCH(1, 1);

    int s = 0, sp = 2;
    for (int c = 0; c < NCHUNK; c++) {
        if (c + 1 < NCHUNK) CP_WAIT1(); else CP_WAIT0();
        __syncthreads();
        if (c + 2 < NCHUNK) PREFETCH(c + 2, sp);

        const uint32_t abase = smem + s * STAGE2;
        const uint32_t bbase = abase + A_ST;

#pragma unroll
        for (int ks = 0; ks < 4; ks++) {
            uint32_t a[4][4];
#pragma unroll
            for (int mf = 0; mf < 4; mf++) {
                int row = arow + mf * 16;
                uint32_t addr = abase + row * 128 +
                    ((ks * 32 + acb0) ^ ((row & 7) << 4));
                LDMATRIX_X4(a[mf][0], a[mf][1], a[mf][2], a[mf][3], addr);
            }
#pragma unroll
            for (int nf2 = 0; nf2 < 4; nf2++) {
                int row = brow0 + nf2 * 16;
                uint32_t addr = bbase + row * 128 +
                    ((ks * 32 + bcb0) ^ ((row & 7) << 4));
                uint32_t r0, r1, r2, r3;
                LDMATRIX_X4(r0, r1, r2, r3, addr);
                uint32_t b0[2] = {r0, r1}, b1[2] = {r2, r3};
#pragma unroll
                for (int mf = 0; mf < 4; mf++) {
                    MMA_F16(acc[mf][nf2 * 2],     a[mf], b0);
                    MMA_F16(acc[mf][nf2 * 2 + 1], a[mf], b1);
                }
            }
        }
        s  = (s  == 2) ? 0 : s + 1;
        sp = (sp == 2) ? 0 : sp + 1;
    }
#undef PREFETCH

    // fused QKV epilogue (q scaled into log2 domain for exp2 softmax)
    const int w     = n0 >> 10;            // 0=q, 1=k, 2=v
    const int cbase = n0 & 1023;
#pragma unroll
    for (int mf = 0; mf < 4; mf++) {
        const int r0r = m0 + wm * 64 + mf * 16 + (lane >> 2);
#pragma unroll
        for (int nf = 0; nf < 8; nf++) {
            const int cN = cbase + wn * 64 + nf * 8 + (lane & 3) * 2;
            const int j  = (cN & 63) >> 1;
            if (w == 2) {
#pragma unroll
                for (int rr = 0; rr < 2; rr++) {
                    const int r = r0r + rr * 8;
                    *(__half2*)(vh + (size_t)r * D_ + cN) =
                        __floats2half2_rn(acc[mf][nf][rr * 2],
                                          acc[mf][nf][rr * 2 + 1]);
                }
            } else {
                __half* dst = (w == 0) ? qh : kh;
                const float qs = (w == 0) ? (0.125f * LOG2E) : 1.0f;
#pragma unroll
                for (int rr = 0; rr < 2; rr++) {
                    const int r = r0r + rr * 8;
                    const int srow = r & (S_ - 1);
                    const float cv = fc[srow * 32 + j];
                    const float sv = fs[srow * 32 + j];
                    float x0 = acc[mf][nf][rr * 2], x1 = acc[mf][nf][rr * 2 + 1];
                    *(__half2*)(dst + (size_t)r * D_ + cN) =
                        __floats2half2_rn((x0 * cv - x1 * sv) * qs,
                                          (x1 * cv + x0 * sv) * qs);
                }
            }
        }
    }
}

// ---------------------------------------------------------------------------
// Fused attention + output projection (producer/consumer overlap).
// pids 0..511:  flash attention (R14 config: two independent 4-warp groups,
//               64-row q-tiles, k-tile 128, 3-stage). jq-major heavy-first so
//               all heads of a 128-row block finish together; each group
//               signals g_sync[row_block] after writing its ac rows.
// pids 512..639: proj GEMM M-block; spins until its 32 producer signals,
//               then computes out = ac @ Wo^T (mode-1 GEMM body).
// ---------------------------------------------------------------------------
#define ATT_GQ    8192
#define ATT_STAGE 32768
#define ATT_SMEM  (2 * ATT_GQ + 2 * 3 * ATT_STAGE)   // 208 KB

__global__ __launch_bounds__(256) void attn_proj_kernel(
    const __half* __restrict__ qh, const __half* __restrict__ kh,
    const __half* __restrict__ vh, __half* __restrict__ oc,
    const __half* __restrict__ wo, float* __restrict__ out,
    int* __restrict__ syncp)
{
    extern __shared__ char dyn[];
    const int pid  = blockIdx.x;
    const int tid  = threadIdx.x;
    const int wid  = tid >> 5;
    const int lane = tid & 31;
    const uint32_t smem = smem_u32(dyn);

    if (pid < 512) {
        // ================= attention =================
        const int grp  = wid >> 2;
        const int wg   = wid & 3;
        const int gt   = tid & 127;
        const int jqp  = 15 - (pid >> 5);          // heavy q-blocks first
        const int bh   = pid & 31;
        const int jq   = 2 * jqp + grp;
        const int b  = bh >> 4;
        const int h  = bh & 15;
        const size_t base = (size_t)b * S_ * D_ + (size_t)h * HD_;
        const uint32_t qbase = smem + grp * ATT_GQ;
        const uint32_t sbase = smem + 2 * ATT_GQ + grp * 3 * ATT_STAGE;
        const int barid = grp + 1;

        const int lrow = gt >> 3;
        const int lc16 = gt & 7;
        const __half* gq = qh + base + (size_t)(jq * 64 + lrow) * D_ + lc16 * 8;
        const __half* gk = kh + base + (size_t)lrow * D_ + lc16 * 8;
        const __half* gv = vh + base + (size_t)lrow * D_ + lc16 * 8;

        const int ktmax = (jq * 64 + 63) >> 7;

#pragma unroll
        for (int t = 0; t < 4; t++) {
            int row = lrow + t * 16;
            CP_ASYNC16(qbase + sw128(row * 128 + lc16 * 16),
                       gq + (size_t)t * 16 * D_);
        }

#define ATT_PREFETCH_NC(kt, stg) do {                                           \
    uint32_t sb = sbase + (stg) * ATT_STAGE;                                    \
    const __half* pk = gk + (size_t)(kt) * 128 * D_;                            \
    const __half* pv = gv + (size_t)(kt) * 128 * D_;                            \
    _Pragma("unroll")                                                           \
    for (int t = 0; t < 8; t++) {                                               \
        int row = lrow + t * 16;                                                \
        uint32_t so = sw128(row * 128 + lc16 * 16);                             \
        CP_ASYNC16(sb +         so, pk + (size_t)t * 16 * D_);                  \
        CP_ASYNC16(sb + 16384 + so, pv + (size_t)t * 16 * D_);                  \
    } } while (0)

        ATT_PREFETCH_NC(0, 0);
        CP_COMMIT();
        if (ktmax >= 1) { ATT_PREFETCH_NC(1, 1); CP_COMMIT(); }

        float ml = -1e30f, mh = -1e30f, ll = 0.f, lh = 0.f;
        float oacc[8][4];
#pragma unroll
        for (int i = 0; i < 8; i++)
#pragma unroll
            for (int j = 0; j < 4; j++) oacc[i][j] = 0.f;

        const int rowl_g = jq * 64 + wg * 16 + (lane >> 2);

        int s = 0, sp = 2;
        for (int kt = 0; kt <= ktmax; kt++) {
            if (kt + 1 <= ktmax) CP_WAIT1(); else CP_WAIT0();
            BAR_GROUP(barid);
            if (kt + 2 <= ktmax) { ATT_PREFETCH_NC(kt + 2, sp); CP_COMMIT(); }

            const uint32_t kb = sbase + s * ATT_STAGE;
            const uint32_t vb = kb + 16384;

            float sacc[16][4];
#pragma unroll
            for (int nf = 0; nf < 16; nf++)
#pragma unroll
                for (int q4 = 0; q4 < 4; q4++) sacc[nf][q4] = 0.f;

#pragma unroll
            for (int ks = 0; ks < 4; ks++) {
                const int arow = wg * 16 + (lane & 15);
                uint32_t aaddr = qbase + arow * 128 +
                    ((ks * 32 + (lane >> 4) * 16) ^ ((arow & 7) << 4));
                uint32_t a[4];
                LDMATRIX_X4(a[0], a[1], a[2], a[3], aaddr);
#pragma unroll
                for (int nf2 = 0; nf2 < 8; nf2++) {
                    const int brow = nf2 * 16 + (lane & 7) + ((lane >> 4) << 3);
                    uint32_t baddr = kb + brow * 128 +
                        ((ks * 32 + ((lane >> 3) & 1) * 16) ^ ((brow & 7) << 4));
                    uint32_t r0, r1, r2, r3;
                    LDMATRIX_X4(r0, r1, r2, r3, baddr);
                    uint32_t b0[2] = {r0, r1}, b1[2] = {r2, r3};
                    MMA_F16(sacc[nf2 * 2],     a, b0);
                    MMA_F16(sacc[nf2 * 2 + 1], a, b1);
                }
            }

            if (kt == ktmax) {
#pragma unroll
                for (int nf = 0; nf < 16; nf++) {
                    int c0 = kt * 128 + nf * 8 + (lane & 3) * 2;
                    if (c0     > rowl_g)     sacc[nf][0] = -1e30f;
                    if (c0 + 1 > rowl_g)     sacc[nf][1] = -1e30f;
                    if (c0     > rowl_g + 8) sacc[nf][2] = -1e30f;
                    if (c0 + 1 > rowl_g + 8) sacc[nf][3] = -1e30f;
                }
            }

            float tml = -1e30f, tmh = -1e30f;
#pragma unroll
            for (int nf = 0; nf < 16; nf++) {
                tml = fmaxf(tml, fmaxf(sacc[nf][0], sacc[nf][1]));
                tmh = fmaxf(tmh, fmaxf(sacc[nf][2], sacc[nf][3]));
            }
            tml = fmaxf(tml, __shfl_xor_sync(0xffffffffu, tml, 1));
            tml = fmaxf(tml, __shfl_xor_sync(0xffffffffu, tml, 2));
            tmh = fmaxf(tmh, __shfl_xor_sync(0xffffffffu, tmh, 1));
            tmh = fmaxf(tmh, __shfl_xor_sync(0xffffffffu, tmh, 2));

            const float mln = fmaxf(ml, tml), mhn = fmaxf(mh, tmh);
            const float scl = ex2(ml - mln), sch = ex2(mh - mhn);
            ml = mln; mh = mhn;

            uint32_t phl[16], phh[16];
            float sl = 0.f, sh = 0.f;
#pragma unroll
            for (int nf = 0; nf < 16; nf++) {
                float p0 = ex2(sacc[nf][0] - mln);
                float p1 = ex2(sacc[nf][1] - mln);
                float p2 = ex2(sacc[nf][2] - mhn);
                float p3 = ex2(sacc[nf][3] - mhn);
                sl += p0 + p1; sh += p2 + p3;
                phl[nf] = pack_h2(p0, p1);
                phh[nf] = pack_h2(p2, p3);
            }
            sl += __shfl_xor_sync(0xffffffffu, sl, 1);
            sl += __shfl_xor_sync(0xffffffffu, sl, 2);
            sh += __shfl_xor_sync(0xffffffffu, sh, 1);
            sh += __shfl_xor_sync(0xffffffffu, sh, 2);
            ll = ll * scl + sl;
            lh = lh * sch + sh;
#pragma unroll
            for (int onf = 0; onf < 8; onf++) {
                oacc[onf][0] *= scl; oacc[onf][1] *= scl;
                oacc[onf][2] *= sch; oacc[onf][3] *= sch;
            }

#pragma unroll
            for (int ksp = 0; ksp < 8; ksp++) {
                uint32_t a[4] = { phl[2 * ksp], phh[2 * ksp],
                                  phl[2 * ksp + 1], phh[2 * ksp + 1] };
                const int vrow = ksp * 16 + (lane & 7) + ((lane >> 3) & 1) * 8;
#pragma unroll
                for (int nd = 0; nd < 4; nd++) {
                    uint32_t vaddr = vb + vrow * 128 +
                        ((nd * 32 + (lane >> 4) * 16) ^ ((vrow & 7) << 4));
                    uint32_t r0, r1, r2, r3;
                    LDMATRIX_X4_T(r0, r1, r2, r3, vaddr);
                    uint32_t b0[2] = {r0, r1}, b1[2] = {r2, r3};
                    MMA_F16(oacc[nd * 2],     a, b0);
                    MMA_F16(oacc[nd * 2 + 1], a, b1);
                }
            }
            s  = (s  == 2) ? 0 : s + 1;
            sp = (sp == 2) ? 0 : sp + 1;
        }
#undef ATT_PREFETCH_NC

        // epilogue: normalize, write fp16 attn
        const float il = 1.f / ll, ih = 1.f / lh;
        const int rowg = b * S_ + rowl_g;
#pragma unroll
        for (int nf = 0; nf < 8; nf++) {
            const int col = h * HD_ + nf * 8 + (lane & 3) * 2;
            *(__half2*)(oc + (size_t)rowg * D_ + col) =
                __floats2half2_rn(oacc[nf][0] * il, oacc[nf][1] * il);
            *(__half2*)(oc + (size_t)(rowg + 8) * D_ + col) =
                __floats2half2_rn(oacc[nf][2] * ih, oacc[nf][3] * ih);
        }

        // signal: this group's 64 ac rows are done
        BAR_GROUP(barid);
        __threadfence();
        if (gt == 0) atomicAdd(&syncp[b * 16 + jqp], 1);
        return;
    }

    // ================= output projection =================
    {
        const int q  = pid - 512;
        const int bx = q & 3;
        const int by = 31 - (q >> 2);          // ready-first order
        const int m0 = by * 128;
        const int n0 = bx * 256;

        if (tid == 0) {
            volatile int* c = syncp;
            while (c[by] < 32) __nanosleep(128);
            __threadfence();
        }
        __syncthreads();

        const int wm   = wid >> 2;
        const int wn   = wid & 3;
        const int lrow = tid >> 3;
        const int lc16 = tid & 7;
        const __half* gA = oc + (size_t)(m0 + lrow) * 1024 + lc16 * 8;
        const __half* gB = wo + (size_t)(n0 + lrow) * 1024 + lc16 * 8;
        const uint32_t sA0 = smem + sw128(lrow * 128 + lc16 * 16);
        const uint32_t sB0 = sA0 + A_ST;

#define PPREFETCH(c, stg) do {                                                  \
    const __half* pa = gA + (size_t)(c) * 64;                                   \
    const __half* pb = gB + (size_t)(c) * 64;                                   \
    uint32_t off = (stg) * STAGE2;                                              \
    _Pragma("unroll")                                                           \
    for (int j = 0; j < 4; j++)                                                 \
        CP_ASYNC16(sA0 + off + j * 4096, pa + (size_t)j * 32 * 1024);           \
    _Pragma("unroll")                                                           \
    for (int j = 0; j < 8; j++)                                                 \
        CP_ASYNC16(sB0 + off + j * 4096, pb + (size_t)j * 32 * 1024);           \
    CP_COMMIT(); } while (0)

        float acc[4][8][4];
#pragma unroll
        for (int i = 0; i < 4; i++)
#pragma unroll
            for (int j = 0; j < 8; j++)
#pragma unroll
                for (int qq = 0; qq < 4; qq++) acc[i][j][qq] = 0.f;

        const int arow = wm * 64 + (lane & 15);
        const int acb0 = (lane >> 4) * 16;
        const int brow0 = wn * 64 + (lane & 7) + ((lane >> 4) << 3);
        const int bcb0 = ((lane >> 3) & 1) * 16;

        PPREFETCH(0, 0);
        PPREFETCH(1, 1);

        int s = 0, sp = 2;
        for (int c = 0; c < NCHUNK; c++) {
            if (c + 1 < NCHUNK) CP_WAIT1(); else CP_WAIT0();
            __syncthreads();
            if (c + 2 < NCHUNK) PPREFETCH(c + 2, sp);

            const uint32_t abase = smem + s * STAGE2;
            const uint32_t bbase = abase + A_ST;

#pragma unroll
            for (int ks = 0; ks < 4; ks++) {
                uint32_t a[4][4];
#pragma unroll
                for (int mf = 0; mf < 4; mf++) {
                    int row = arow + mf * 16;
                    uint32_t addr = abase + row * 128 +
                        ((ks * 32 + acb0) ^ ((row & 7) << 4));
                    LDMATRIX_X4(a[mf][0], a[mf][1], a[mf][2], a[mf][3], addr);
                }
#pragma unroll
                for (int nf2 = 0; nf2 < 4; nf2++) {
                    int row = brow0 + nf2 * 16;
                    uint32_t addr = bbase + row * 128 +
                        ((ks * 32 + bcb0) ^ ((row & 7) << 4));
                    uint32_t r0, r1, r2, r3;
                    LDMATRIX_X4(r0, r1, r2, r3, addr);
                    uint32_t b0[2] = {r0, r1}, b1[2] = {r2, r3};
#pragma unroll
                    for (int mf = 0; mf < 4; mf++) {
                        MMA_F16(acc[mf][nf2 * 2],     a[mf], b0);
                        MMA_F16(acc[mf][nf2 * 2 + 1], a[mf], b1);
                    }
                }
            }
            s  = (s  == 2) ? 0 : s + 1;
            sp = (sp == 2) ? 0 : sp + 1;
        }
#undef PPREFETCH

#pragma unroll
        for (int mf = 0; mf < 4; mf++) {
            int r = m0 + wm * 64 + mf * 16 + (lane >> 2);
#pragma unroll
            for (int nf = 0; nf < 8; nf++) {
                int cN = n0 + wn * 64 + nf * 8 + (lane & 3) * 2;
                *(float2*)(out + (size_t)r * D_ + cN) =
                    make_float2(acc[mf][nf][0], acc[mf][nf][1]);
                *(float2*)(out + (size_t)(r + 8) * D_ + cN) =
                    make_float2(acc[mf][nf][2], acc[mf][nf][3]);
            }
        }
    }
}

// ---------------------------------------------------------------------------
// kernel_launch
// ---------------------------------------------------------------------------
extern "C" void kernel_launch(void* const* d_in, const int* in_sizes, int n_in,
                              void* d_out, int out_size)
{
    (void)in_sizes; (void)n_in; (void)out_size;
    const float* x  = (const float*)d_in[0];
    const float* fc = (const float*)d_in[1];
    const float* fs = (const float*)d_in[2];
    float* out = (float*)d_out;

    __half *xh, *wc, *ac, *qhp, *khp, *vhp;
    int* sync;
    cudaGetSymbolAddress((void**)&xh, g_xh);
    cudaGetSymbolAddress((void**)&wc, g_wc16);
    cudaGetSymbolAddress((void**)&ac, g_ac16);
    cudaGetSymbolAddress((void**)&qhp, g_qh);
    cudaGetSymbolAddress((void**)&khp, g_kh);
    cudaGetSymbolAddress((void**)&vhp, g_vh);
    cudaGetSymbolAddress((void**)&sync, g_sync);

    cudaFuncSetAttribute(gemm_qkv_kernel,
                         cudaFuncAttributeMaxDynamicSharedMemorySize, GEMM_SMEM);
    cudaFuncSetAttribute(attn_proj_kernel,
                         cudaFuncAttributeMaxDynamicSharedMemorySize, ATT_SMEM);

    // x + all 4 weights -> fp16; zero sync counters
    conv_all_kernel<<<(1 << 22) / 256, 256>>>(
        (const float2*)x,
        (const float2*)d_in[3], (const float2*)d_in[4],
        (const float2*)d_in[5], (const float2*)d_in[6],
        (__half2*)xh, (__half2*)wc);

    // Fused QKV projection + RoPE + v convert (grid 12 x 32)
    gemm_qkv_kernel<<<dim3(12, M_ / 128), 256, GEMM_SMEM>>>(
        xh, wc, qhp, khp, vhp, fc, fs);

    // Fused attention + output projection (producer/consumer overlap)
    attn_proj_kernel<<<640, 256, ATT_SMEM>>>(
        qhp, khp, vhp, ac, wc + (size_t)3 * D_ * D_, out, sync);
}